// round 5
// baseline (speedup 1.0000x reference)
#include <cuda_runtime.h>
#include <cuda_bf16.h>

#define B_BATCH 128
typedef unsigned long long ull;

// Scratch (static device globals — allocation-free per harness rules)
__device__ float g_z1[128 * 64 * 48 * 48];   // conv1 out, NCHW
__device__ float g_z2[128 * 128 * 16 * 16];  // conv2 out, NCHW
__device__ float g_z3[64 * 128 * 13 * 13];   // conv3 out, [C][N] row-major
__device__ float g_cnorm[512];

// ---------------------------------------------------------------------------
// f32x2 packed-FMA helpers (FFMA2 — only reachable via PTX fma.rn.f32x2)
// ---------------------------------------------------------------------------
__device__ __forceinline__ ull pack2(float x, float y) {
    ull r; asm("mov.b64 %0, {%1, %2};" : "=l"(r) : "f"(x), "f"(y)); return r;
}
__device__ __forceinline__ void ffma2(ull& d, ull a, ull b) {
    asm("fma.rn.f32x2 %0, %1, %2, %0;" : "+l"(d) : "l"(a), "l"(b));
}
__device__ __forceinline__ float2 unpack2(ull v) {
    float2 f; asm("mov.b64 {%0, %1}, %2;" : "=f"(f.x), "=f"(f.y) : "l"(v)); return f;
}

// ---------------------------------------------------------------------------
// Implicit-GEMM convolution, FFMA2 datapath, double-buffered smem.
//   C[M=OC, N=B*OH*OW] = W[OC,K] * im2col(X)[K,N],  K = IC*KH*KW
// A staged in smem as DUPLICATED f32x2 pairs (v,v) -> broadcast operand of
// FFMA2. B staged as plain floats; consecutive pairs are the packed operand.
// Micro-tile TM x TN (TN=8 -> 4 f32x2 accumulд pairs per row).
// LAYOUT 0: NCHW out; LAYOUT 1: [oc][n] flat out.
// ---------------------------------------------------------------------------
template <int IC, int KH, int KW, int IH, int IW, int OH, int OW,
          int STRIDE, int PAD, int OC, bool RELU, int LAYOUT,
          int MT, int NT, int THREADS>
__global__ __launch_bounds__(THREADS) void conv_gemm2(
    const float* __restrict__ x, const float* __restrict__ w,
    const float* __restrict__ bias, float* __restrict__ out)
{
    constexpr int K     = IC * KH * KW;
    constexpr int OHW   = OH * OW;
    constexpr int NTOT  = B_BATCH * OHW;
    constexpr int KT    = 8;                 // K-tile
    constexpr int TN    = 8;                 // per-thread n (4 f32x2)
    constexpr int BN    = NT / TN;
    constexpr int BM    = THREADS / BN;
    constexpr int TM    = MT / BM;           // per-thread m
    constexpr int AEPT  = MT * KT / THREADS; // A elems/thread (2 or 4)
    constexpr int A_TPR = KT / AEPT;
    constexpr int PA    = MT + 2;            // even pad -> 16B row alignment
    constexpr int NTILES = K / KT;
    static_assert(K % KT == 0, "K tile");
    static_assert(THREADS / NT == 2, "B loader shape");

    __shared__ __align__(16) ull   As2[2][KT][PA];
    __shared__ __align__(16) float Bs [2][KT][NT];

    const int tid = threadIdx.x;
    const int tx  = tid % BN;
    const int ty  = tid / BN;
    const int m0  = blockIdx.y * MT;
    const int n0  = blockIdx.x * NT;

    // --- B-tile loader coords (fixed n per thread, 4 k-slices of stride 2) ---
    const int bn  = tid % NT;
    const int kb  = tid / NT;                // 0..1
    const int ng  = n0 + bn;
    const int nb  = ng / OHW;
    const int np  = ng % OHW;
    const int ih0 = (np / OW) * STRIDE - PAD;
    const int iw0 = (np % OW) * STRIDE - PAD;
    const float* xb = x + (size_t)nb * (IC * IH * IW);

    // --- A-tile loader coords ---
    const int am = tid / A_TPR;
    const int ak = (tid % A_TPR) * AEPT;
    const float* wrow = w + (size_t)(m0 + am) * K + ak;

    ull acc[TM][TN / 2];
#pragma unroll
    for (int i = 0; i < TM; i++)
#pragma unroll
        for (int j = 0; j < TN / 2; j++) acc[i][j] = 0ull;

    float areg[AEPT];
    float breg[4];

    auto loadA = [&](int k0) {
        if (AEPT == 4) {
            float4 v = *reinterpret_cast<const float4*>(wrow + k0);
            areg[0] = v.x; areg[1] = v.y; areg[2] = v.z; areg[3] = v.w;
        } else {
            float2 v = *reinterpret_cast<const float2*>(wrow + k0);
            areg[0] = v.x; areg[1] = v.y;
        }
    };
    auto loadB = [&](int k0) {
#pragma unroll
        for (int i = 0; i < 4; i++) {
            const int kg = k0 + kb + i * 2;
            const int ic = kg / (KH * KW);
            const int r  = kg % (KH * KW);
            const int ih = ih0 + r / KW;
            const int iw = iw0 + r % KW;
            float v = 0.f;
            if (ih >= 0 && ih < IH && iw >= 0 && iw < IW)
                v = __ldg(xb + (ic * IH + ih) * IW + iw);
            breg[i] = v;
        }
    };
    auto storeTile = [&](int st) {
#pragma unroll
        for (int i = 0; i < AEPT; i++)
            As2[st][ak + i][am] = pack2(areg[i], areg[i]);
#pragma unroll
        for (int i = 0; i < 4; i++)
            Bs[st][kb + i * 2][bn] = breg[i];
    };
    auto compute = [&](int st) {
#pragma unroll
        for (int k = 0; k < KT; k++) {
            ull a[TM], b[TN / 2];
#pragma unroll
            for (int i = 0; i < TM; i += 2) {
                ulonglong2 av = *reinterpret_cast<const ulonglong2*>(&As2[st][k][ty * TM + i]);
                a[i] = av.x; a[i + 1] = av.y;
            }
#pragma unroll
            for (int j = 0; j < TN / 2; j += 2) {
                ulonglong2 bv = *reinterpret_cast<const ulonglong2*>(&Bs[st][k][tx * TN + j * 2]);
                b[j] = bv.x; b[j + 1] = bv.y;
            }
#pragma unroll
            for (int i = 0; i < TM; i++)
#pragma unroll
                for (int j = 0; j < TN / 2; j++)
                    ffma2(acc[i][j], a[i], b[j]);
        }
    };

    // ---- double-buffered mainloop ----
    loadA(0); loadB(0); storeTile(0);
    __syncthreads();
#pragma unroll 1
    for (int t = 1; t < NTILES; t++) {
        loadA(t * KT);
        loadB(t * KT);
        compute((t - 1) & 1);
        storeTile(t & 1);
        __syncthreads();
    }
    compute((NTILES - 1) & 1);

    // ---- epilogue: bias (+ReLU), 2x float4 per row ----
    const int nout = n0 + tx * TN;
    const int bo   = nout / OHW;       // NT divides OHW (layout 0 cases)
    const int po   = nout % OHW;
#pragma unroll
    for (int i = 0; i < TM; i++) {
        const int oc = m0 + ty * TM + i;
        const float bv = __ldg(bias + oc);
        float vals[TN];
#pragma unroll
        for (int j = 0; j < TN / 2; j++) {
            float2 p = unpack2(acc[i][j]);
            float v0 = p.x + bv, v1 = p.y + bv;
            if (RELU) { v0 = fmaxf(v0, 0.f); v1 = fmaxf(v1, 0.f); }
            vals[2 * j] = v0; vals[2 * j + 1] = v1;
        }
        float* dst = (LAYOUT == 0)
            ? out + (size_t)(bo * OC + oc) * OHW + po
            : out + (size_t)oc * NTOT + nout;
        *reinterpret_cast<float4*>(dst)     = make_float4(vals[0], vals[1], vals[2], vals[3]);
        *reinterpret_cast<float4*>(dst + 4) = make_float4(vals[4], vals[5], vals[6], vals[7]);
    }
}

// ---------------------------------------------------------------------------
// Codebook squared norms
// ---------------------------------------------------------------------------
__global__ void cnorm_kernel(const float* __restrict__ cb)
{
    const int i = blockIdx.x * blockDim.x + threadIdx.x;
    if (i < 512) {
        float s = 0.f;
#pragma unroll
        for (int c = 0; c < 64; c++) {
            const float v = cb[i * 64 + c];
            s += v * v;
        }
        g_cnorm[i] = s;
    }
}

// ---------------------------------------------------------------------------
// VQ argmin + one-hot scatter, FFMA2 inner product.
// z3 layout [64][21632]; score = ||c||^2 - 2 z.c  (||z||^2 row-constant).
// Strict < keeps first minimum (jnp.argmin tie-break).
// ---------------------------------------------------------------------------
__global__ __launch_bounds__(128) void argmin_onehot_kernel(
    const float* __restrict__ cb, float* __restrict__ out)
{
    __shared__ __align__(16) float cbs[128 * 64];
    __shared__ float cns[128];

    const int tid = threadIdx.x;
    const int n   = blockIdx.x * 128 + tid;

    ull zr2[32];
#pragma unroll
    for (int c = 0; c < 32; c++)
        zr2[c] = pack2(g_z3[(2 * c) * 21632 + n], g_z3[(2 * c + 1) * 21632 + n]);

    float best = 3.4e38f;
    int   bidx = 0;

    for (int t = 0; t < 4; t++) {
        __syncthreads();
        const float4* src = reinterpret_cast<const float4*>(cb + t * 128 * 64);
        float4* dst = reinterpret_cast<float4*>(cbs);
#pragma unroll
        for (int i = 0; i < 16; i++)
            dst[tid + i * 128] = src[tid + i * 128];
        cns[tid] = g_cnorm[t * 128 + tid];
        __syncthreads();

#pragma unroll 4
        for (int j = 0; j < 128; j++) {
            const ull* cr = reinterpret_cast<const ull*>(cbs + j * 64);
            ull d0 = 0, d1 = 0, d2 = 0, d3 = 0;
#pragma unroll
            for (int c = 0; c < 32; c += 4) {
                ulonglong2 c01 = *reinterpret_cast<const ulonglong2*>(cr + c);
                ulonglong2 c23 = *reinterpret_cast<const ulonglong2*>(cr + c + 2);
                ffma2(d0, zr2[c + 0], c01.x);
                ffma2(d1, zr2[c + 1], c01.y);
                ffma2(d2, zr2[c + 2], c23.x);
                ffma2(d3, zr2[c + 3], c23.y);
            }
            float2 p0 = unpack2(d0), p1 = unpack2(d1);
            float2 p2 = unpack2(d2), p3 = unpack2(d3);
            const float s = ((p0.x + p0.y) + (p1.x + p1.y))
                          + ((p2.x + p2.y) + (p3.x + p3.y));
            const float score = cns[j] - 2.f * s;
            const int gidx = t * 128 + j;
            if (score < best) { best = score; bidx = gidx; }
        }
    }

    const int b = n / 169;
    const int p = n % 169;
    out[((size_t)b * 512 + bidx) * 169 + p] = 1.0f;
}

// ---------------------------------------------------------------------------
extern "C" void kernel_launch(void* const* d_in, const int* in_sizes, int n_in,
                              void* d_out, int out_size)
{
    const float* x  = (const float*)d_in[0];
    const float* w1 = (const float*)d_in[1];
    const float* b1 = (const float*)d_in[2];
    const float* w2 = (const float*)d_in[3];
    const float* b2 = (const float*)d_in[4];
    const float* w3 = (const float*)d_in[5];
    const float* b3 = (const float*)d_in[6];
    const float* cb = (const float*)d_in[7];
    float* out = (float*)d_out;

    float *z1, *z2, *z3;
    cudaGetSymbolAddress((void**)&z1, g_z1);
    cudaGetSymbolAddress((void**)&z2, g_z2);
    cudaGetSymbolAddress((void**)&z3, g_z3);

    // output is a one-hot: zero it, scatter the ones later
    cudaMemsetAsync(out, 0, (size_t)out_size * sizeof(float));

    // conv1: 3->64, 8x8 s4 p2, 192->48, ReLU, NCHW.  N = 294912, tile 64x128
    conv_gemm2<3, 8, 8, 192, 192, 48, 48, 4, 2, 64, true, 0, 64, 128, 256>
        <<<dim3(294912 / 128, 1), 256>>>(x, w1, b1, z1);

    // conv2: 64->128, 6x6 s3 p2, 48->16, ReLU, NCHW.  N = 32768, tile 128x128
    conv_gemm2<64, 6, 6, 48, 48, 16, 16, 3, 2, 128, true, 0, 128, 128, 256>
        <<<dim3(32768 / 128, 1), 256>>>(z1, w2, b2, z2);

    // conv3: 128->64, 4x4 s1 p0, 16->13, no ReLU, [C][N].  N = 21632, tile 64x64
    conv_gemm2<128, 4, 4, 16, 16, 13, 13, 1, 0, 64, false, 1, 64, 64, 128>
        <<<dim3(21632 / 64, 1), 128>>>(z2, w3, b3, z3);

    cnorm_kernel<<<2, 256>>>(cb);

    argmin_onehot_kernel<<<21632 / 128, 128>>>(cb, out);
}

// round 9
// speedup vs baseline: 1.0340x; 1.0340x over previous
#include <cuda_runtime.h>
#include <cuda_bf16.h>

#define B_BATCH 128
typedef unsigned long long ull;

// Scratch (static device globals — allocation-free per harness rules)
__device__ float g_z1[128 * 64 * 48 * 48];   // conv1 out, NCHW
__device__ float g_z2[128 * 128 * 16 * 16];  // conv2 out, NCHW
__device__ float g_z3[64 * 128 * 13 * 13];   // conv3 out, [C][N] row-major
__device__ float g_cnorm[512];

// ---------------------------------------------------------------------------
// f32x2 packed-FMA helpers (FFMA2 — only reachable via PTX fma.rn.f32x2)
// ---------------------------------------------------------------------------
__device__ __forceinline__ ull pack2(float x, float y) {
    ull r; asm("mov.b64 %0, {%1, %2};" : "=l"(r) : "f"(x), "f"(y)); return r;
}
__device__ __forceinline__ void ffma2(ull& d, ull a, ull b) {
    asm("fma.rn.f32x2 %0, %1, %2, %0;" : "+l"(d) : "l"(a), "l"(b));
}
__device__ __forceinline__ float2 unpack2(ull v) {
    float2 f; asm("mov.b64 {%0, %1}, %2;" : "=f"(f.x), "=f"(f.y) : "l"(v)); return f;
}

// ---------------------------------------------------------------------------
// Implicit-GEMM convolution — R3 structure (64x64 tile, KT=16, 256 thr,
// 4x4 micro-tile, single smem buffer) with:
//   * FFMA2 inner product (A duplicated (v,v) pairs in smem)
//   * register prefetch of tile t+1 gmem loads during compute of tile t
// LAYOUT 0: NCHW out; LAYOUT 1: [oc][n] flat out.
// ---------------------------------------------------------------------------
template <int IC, int KH, int KW, int IH, int IW, int OH, int OW,
          int STRIDE, int PAD, int OC, bool RELU, int LAYOUT>
__global__ __launch_bounds__(256) void conv_gemm_kernel(
    const float* __restrict__ x, const float* __restrict__ w,
    const float* __restrict__ bias, float* __restrict__ out)
{
    constexpr int K      = IC * KH * KW;
    constexpr int OHW    = OH * OW;
    constexpr int NTOT   = B_BATCH * OHW;
    constexpr int NTILES = K / 16;
    static_assert(K % 16 == 0, "K tile");

    __shared__ __align__(16) ull   As2[16][66];  // duplicated pairs, padded rows
    __shared__ __align__(16) float Bs [16][64];

    const int tid = threadIdx.x;
    const int tx  = tid & 15;      // N direction
    const int ty  = tid >> 4;      // M direction

    const int m0 = blockIdx.y * 64;
    const int n0 = blockIdx.x * 64;

    // --- B-tile loader coords (fixed n per thread across K loop) ---
    const int bn  = tid & 63;
    const int bk  = tid >> 6;            // 0..3
    const int ng  = n0 + bn;
    const int nb  = ng / OHW;
    const int np  = ng % OHW;
    const int oh  = np / OW;
    const int ow  = np % OW;
    const int ih0 = oh * STRIDE - PAD;
    const int iw0 = ow * STRIDE - PAD;
    const float* xb = x + (size_t)nb * (IC * IH * IW);

    // --- A-tile loader coords ---
    const int am = tid >> 2;             // 0..63
    const int ak = (tid & 3) * 4;        // 0,4,8,12
    const float* wrow = w + (size_t)(m0 + am) * K;

    ull acc[4][2];
#pragma unroll
    for (int i = 0; i < 4; i++) { acc[i][0] = 0ull; acc[i][1] = 0ull; }

    float4 areg;
    float  breg[4];

    auto loadA = [&](int k0) {
        areg = *reinterpret_cast<const float4*>(wrow + k0 + ak);
    };
    auto loadB = [&](int k0) {
#pragma unroll
        for (int i = 0; i < 4; i++) {
            const int kg = k0 + bk + i * 4;
            const int ic = kg / (KH * KW);
            const int r  = kg % (KH * KW);
            const int ih = ih0 + r / KW;
            const int iw = iw0 + r % KW;
            float v = 0.f;
            if (ih >= 0 && ih < IH && iw >= 0 && iw < IW)
                v = xb[(ic * IH + ih) * IW + iw];
            breg[i] = v;
        }
    };
    auto storeTile = [&]() {
        As2[ak + 0][am] = pack2(areg.x, areg.x);
        As2[ak + 1][am] = pack2(areg.y, areg.y);
        As2[ak + 2][am] = pack2(areg.z, areg.z);
        As2[ak + 3][am] = pack2(areg.w, areg.w);
#pragma unroll
        for (int i = 0; i < 4; i++)
            Bs[bk + i * 4][bn] = breg[i];
    };
    auto compute = [&]() {
#pragma unroll
        for (int k = 0; k < 16; k++) {
            ulonglong2 a01 = *reinterpret_cast<const ulonglong2*>(&As2[k][ty * 4]);
            ulonglong2 a23 = *reinterpret_cast<const ulonglong2*>(&As2[k][ty * 4 + 2]);
            ulonglong2 bv  = *reinterpret_cast<const ulonglong2*>(&Bs[k][tx * 4]);
            ffma2(acc[0][0], a01.x, bv.x); ffma2(acc[0][1], a01.x, bv.y);
            ffma2(acc[1][0], a01.y, bv.x); ffma2(acc[1][1], a01.y, bv.y);
            ffma2(acc[2][0], a23.x, bv.x); ffma2(acc[2][1], a23.x, bv.y);
            ffma2(acc[3][0], a23.y, bv.x); ffma2(acc[3][1], a23.y, bv.y);
        }
    };

    // ---- software-pipelined mainloop (single smem buffer, reg prefetch) ----
    loadA(0); loadB(0);
#pragma unroll 1
    for (int t = 0; t < NTILES; t++) {
        storeTile();
        __syncthreads();
        if (t + 1 < NTILES) {             // prefetch next tile during compute
            loadA((t + 1) * 16);
            loadB((t + 1) * 16);
        }
        compute();
        __syncthreads();
    }

    // --- epilogue: bias (+ReLU), vectorized store ---
    const int nout  = n0 + tx * 4;        // 4 consecutive n (OHW % 64 == 0 for LAYOUT 0)
    const int b_out = nout / OHW;
    const int p_out = nout % OHW;
#pragma unroll
    for (int i = 0; i < 4; i++) {
        const int oc = m0 + ty * 4 + i;
        const float bval = bias[oc];
        float2 p0 = unpack2(acc[i][0]);
        float2 p1 = unpack2(acc[i][1]);
        float4 v = make_float4(p0.x + bval, p0.y + bval, p1.x + bval, p1.y + bval);
        if (RELU) {
            v.x = fmaxf(v.x, 0.f); v.y = fmaxf(v.y, 0.f);
            v.z = fmaxf(v.z, 0.f); v.w = fmaxf(v.w, 0.f);
        }
        if (LAYOUT == 0) {
            *reinterpret_cast<float4*>(out + (size_t)(b_out * OC + oc) * OHW + p_out) = v;
        } else {
            *reinterpret_cast<float4*>(out + (size_t)oc * NTOT + nout) = v;
        }
    }
}

// ---------------------------------------------------------------------------
// Codebook squared norms
// ---------------------------------------------------------------------------
__global__ void cnorm_kernel(const float* __restrict__ cb)
{
    const int i = blockIdx.x * blockDim.x + threadIdx.x;
    if (i < 512) {
        float s = 0.f;
#pragma unroll
        for (int c = 0; c < 64; c++) {
            const float v = cb[i * 64 + c];
            s += v * v;
        }
        g_cnorm[i] = s;
    }
}

// ---------------------------------------------------------------------------
// VQ argmin + one-hot scatter, FFMA2 inner product, LDS.128 codebook reads.
// z3 layout [64][21632]; score = ||c||^2 - 2 z.c  (||z||^2 row-constant).
// Strict < keeps first minimum (jnp.argmin tie-break).
// ---------------------------------------------------------------------------
__global__ __launch_bounds__(128) void argmin_onehot_kernel(
    const float* __restrict__ cb, float* __restrict__ out)
{
    __shared__ __align__(16) float cbs[128 * 64];
    __shared__ float cns[128];

    const int tid = threadIdx.x;
    const int n   = blockIdx.x * 128 + tid;

    ull zr2[32];
#pragma unroll
    for (int c = 0; c < 32; c++)
        zr2[c] = pack2(g_z3[(2 * c) * 21632 + n], g_z3[(2 * c + 1) * 21632 + n]);

    float best = 3.4e38f;
    int   bidx = 0;

    for (int t = 0; t < 4; t++) {
        __syncthreads();
        const float4* src = reinterpret_cast<const float4*>(cb + t * 128 * 64);
        float4* dst = reinterpret_cast<float4*>(cbs);
#pragma unroll
        for (int i = 0; i < 16; i++)
            dst[tid + i * 128] = src[tid + i * 128];
        cns[tid] = g_cnorm[t * 128 + tid];
        __syncthreads();

#pragma unroll 4
        for (int j = 0; j < 128; j++) {
            const ull* cr = reinterpret_cast<const ull*>(cbs + j * 64);
            ull d0 = 0, d1 = 0, d2 = 0, d3 = 0;
#pragma unroll
            for (int c = 0; c < 32; c += 4) {
                ulonglong2 c01 = *reinterpret_cast<const ulonglong2*>(cr + c);
                ulonglong2 c23 = *reinterpret_cast<const ulonglong2*>(cr + c + 2);
                ffma2(d0, zr2[c + 0], c01.x);
                ffma2(d1, zr2[c + 1], c01.y);
                ffma2(d2, zr2[c + 2], c23.x);
                ffma2(d3, zr2[c + 3], c23.y);
            }
            float2 p0 = unpack2(d0), p1 = unpack2(d1);
            float2 p2 = unpack2(d2), p3 = unpack2(d3);
            const float s = ((p0.x + p0.y) + (p1.x + p1.y))
                          + ((p2.x + p2.y) + (p3.x + p3.y));
            const float score = cns[j] - 2.f * s;
            const int gidx = t * 128 + j;
            if (score < best) { best = score; bidx = gidx; }
        }
    }

    const int b = n / 169;
    const int p = n % 169;
    out[((size_t)b * 512 + bidx) * 169 + p] = 1.0f;
}

// ---------------------------------------------------------------------------
extern "C" void kernel_launch(void* const* d_in, const int* in_sizes, int n_in,
                              void* d_out, int out_size)
{
    const float* x  = (const float*)d_in[0];
    const float* w1 = (const float*)d_in[1];
    const float* b1 = (const float*)d_in[2];
    const float* w2 = (const float*)d_in[3];
    const float* b2 = (const float*)d_in[4];
    const float* w3 = (const float*)d_in[5];
    const float* b3 = (const float*)d_in[6];
    const float* cb = (const float*)d_in[7];
    float* out = (float*)d_out;

    float *z1, *z2, *z3;
    cudaGetSymbolAddress((void**)&z1, g_z1);
    cudaGetSymbolAddress((void**)&z2, g_z2);
    cudaGetSymbolAddress((void**)&z3, g_z3);

    // output is a one-hot: zero it, scatter the ones later
    cudaMemsetAsync(out, 0, (size_t)out_size * sizeof(float));

    // conv1: 3->64, 8x8 s4 p2, 192->48, ReLU, NCHW.  N = 128*2304 = 294912
    conv_gemm_kernel<3, 8, 8, 192, 192, 48, 48, 4, 2, 64, true, 0>
        <<<dim3(294912 / 64, 1), 256>>>(x, w1, b1, z1);

    // conv2: 64->128, 6x6 s3 p2, 48->16, ReLU, NCHW.  N = 128*256 = 32768
    conv_gemm_kernel<64, 6, 6, 48, 48, 16, 16, 3, 2, 128, true, 0>
        <<<dim3(32768 / 64, 2), 256>>>(z1, w2, b2, z2);

    // conv3: 128->64, 4x4 s1 p0, 16->13, no ReLU, [C][N].  N = 128*169 = 21632
    conv_gemm_kernel<128, 4, 4, 16, 16, 13, 13, 1, 0, 64, false, 1>
        <<<dim3(21632 / 64, 1), 256>>>(z2, w3, b3, z3);

    cnorm_kernel<<<2, 256>>>(cb);

    argmin_onehot_kernel<<<21632 / 128, 128>>>(cb, out);
}

// round 12
// speedup vs baseline: 1.0360x; 1.0019x over previous
#include <cuda_runtime.h>
#include <cuda_bf16.h>

#define B_BATCH 128
typedef unsigned long long ull;

// Scratch (static device globals — allocation-free per harness rules)
__device__ float g_z1[128 * 64 * 48 * 48];   // conv1 out, NCHW
__device__ float g_z2[128 * 128 * 16 * 16];  // conv2 out, NCHW
__device__ float g_z3[64 * 128 * 13 * 13];   // conv3 out, [C][N] row-major
__device__ float g_cnorm[512];

// ---------------------------------------------------------------------------
// f32x2 packed-FMA helpers (FFMA2 — only reachable via PTX fma.rn.f32x2)
// ---------------------------------------------------------------------------
__device__ __forceinline__ ull pack2(float x, float y) {
    ull r; asm("mov.b64 %0, {%1, %2};" : "=l"(r) : "f"(x), "f"(y)); return r;
}
__device__ __forceinline__ void ffma2(ull& d, ull a, ull b) {
    asm("fma.rn.f32x2 %0, %1, %2, %0;" : "+l"(d) : "l"(a), "l"(b));
}
__device__ __forceinline__ float2 unpack2(ull v) {
    float2 f; asm("mov.b64 {%0, %1}, %2;" : "=f"(f.x), "=f"(f.y) : "l"(v)); return f;
}

// ---------------------------------------------------------------------------
// Implicit-GEMM convolution — R3 structure (64x64 tile, KT=16, 256 thr,
// 4x4 micro-tile, single smem buffer) with:
//   * FFMA2 inner product (A duplicated (v,v) pairs in smem)
//   * register prefetch of tile t+1 gmem loads during compute of tile t
// LAYOUT 0: NCHW out; LAYOUT 1: [oc][n] flat out.
// ---------------------------------------------------------------------------
template <int IC, int KH, int KW, int IH, int IW, int OH, int OW,
          int STRIDE, int PAD, int OC, bool RELU, int LAYOUT>
__global__ __launch_bounds__(256) void conv_gemm_kernel(
    const float* __restrict__ x, const float* __restrict__ w,
    const float* __restrict__ bias, float* __restrict__ out)
{
    constexpr int K      = IC * KH * KW;
    constexpr int OHW    = OH * OW;
    constexpr int NTOT   = B_BATCH * OHW;
    constexpr int NTILES = K / 16;
    static_assert(K % 16 == 0, "K tile");

    __shared__ __align__(16) ull   As2[16][66];  // duplicated pairs, padded rows
    __shared__ __align__(16) float Bs [16][64];

    const int tid = threadIdx.x;
    const int tx  = tid & 15;      // N direction
    const int ty  = tid >> 4;      // M direction

    const int m0 = blockIdx.y * 64;
    const int n0 = blockIdx.x * 64;

    // --- B-tile loader coords (fixed n per thread across K loop) ---
    const int bn  = tid & 63;
    const int bk  = tid >> 6;            // 0..3
    const int ng  = n0 + bn;
    const int nb  = ng / OHW;
    const int np  = ng % OHW;
    const int oh  = np / OW;
    const int ow  = np % OW;
    const int ih0 = oh * STRIDE - PAD;
    const int iw0 = ow * STRIDE - PAD;
    const float* xb = x + (size_t)nb * (IC * IH * IW);

    // --- A-tile loader coords ---
    const int am = tid >> 2;             // 0..63
    const int ak = (tid & 3) * 4;        // 0,4,8,12
    const float* wrow = w + (size_t)(m0 + am) * K;

    ull acc[4][2];
#pragma unroll
    for (int i = 0; i < 4; i++) { acc[i][0] = 0ull; acc[i][1] = 0ull; }

    float4 areg;
    float  breg[4];

    auto loadA = [&](int k0) {
        areg = *reinterpret_cast<const float4*>(wrow + k0 + ak);
    };
    auto loadB = [&](int k0) {
#pragma unroll
        for (int i = 0; i < 4; i++) {
            const int kg = k0 + bk + i * 4;
            const int ic = kg / (KH * KW);
            const int r  = kg % (KH * KW);
            const int ih = ih0 + r / KW;
            const int iw = iw0 + r % KW;
            float v = 0.f;
            if (ih >= 0 && ih < IH && iw >= 0 && iw < IW)
                v = xb[(ic * IH + ih) * IW + iw];
            breg[i] = v;
        }
    };
    auto storeTile = [&]() {
        As2[ak + 0][am] = pack2(areg.x, areg.x);
        As2[ak + 1][am] = pack2(areg.y, areg.y);
        As2[ak + 2][am] = pack2(areg.z, areg.z);
        As2[ak + 3][am] = pack2(areg.w, areg.w);
#pragma unroll
        for (int i = 0; i < 4; i++)
            Bs[bk + i * 4][bn] = breg[i];
    };
    auto compute = [&]() {
#pragma unroll
        for (int k = 0; k < 16; k++) {
            ulonglong2 a01 = *reinterpret_cast<const ulonglong2*>(&As2[k][ty * 4]);
            ulonglong2 a23 = *reinterpret_cast<const ulonglong2*>(&As2[k][ty * 4 + 2]);
            ulonglong2 bv  = *reinterpret_cast<const ulonglong2*>(&Bs[k][tx * 4]);
            ffma2(acc[0][0], a01.x, bv.x); ffma2(acc[0][1], a01.x, bv.y);
            ffma2(acc[1][0], a01.y, bv.x); ffma2(acc[1][1], a01.y, bv.y);
            ffma2(acc[2][0], a23.x, bv.x); ffma2(acc[2][1], a23.x, bv.y);
            ffma2(acc[3][0], a23.y, bv.x); ffma2(acc[3][1], a23.y, bv.y);
        }
    };

    // ---- software-pipelined mainloop (single smem buffer, reg prefetch) ----
    loadA(0); loadB(0);
#pragma unroll 1
    for (int t = 0; t < NTILES; t++) {
        storeTile();
        __syncthreads();
        if (t + 1 < NTILES) {             // prefetch next tile during compute
            loadA((t + 1) * 16);
            loadB((t + 1) * 16);
        }
        compute();
        __syncthreads();
    }

    // --- epilogue: bias (+ReLU), vectorized store ---
    const int nout  = n0 + tx * 4;        // 4 consecutive n (OHW % 64 == 0 for LAYOUT 0)
    const int b_out = nout / OHW;
    const int p_out = nout % OHW;
#pragma unroll
    for (int i = 0; i < 4; i++) {
        const int oc = m0 + ty * 4 + i;
        const float bval = bias[oc];
        float2 p0 = unpack2(acc[i][0]);
        float2 p1 = unpack2(acc[i][1]);
        float4 v = make_float4(p0.x + bval, p0.y + bval, p1.x + bval, p1.y + bval);
        if (RELU) {
            v.x = fmaxf(v.x, 0.f); v.y = fmaxf(v.y, 0.f);
            v.z = fmaxf(v.z, 0.f); v.w = fmaxf(v.w, 0.f);
        }
        if (LAYOUT == 0) {
            *reinterpret_cast<float4*>(out + (size_t)(b_out * OC + oc) * OHW + p_out) = v;
        } else {
            *reinterpret_cast<float4*>(out + (size_t)oc * NTOT + nout) = v;
        }
    }
}

// ---------------------------------------------------------------------------
// Codebook squared norms
// ---------------------------------------------------------------------------
__global__ void cnorm_kernel(const float* __restrict__ cb)
{
    const int i = blockIdx.x * blockDim.x + threadIdx.x;
    if (i < 512) {
        float s = 0.f;
#pragma unroll
        for (int c = 0; c < 64; c++) {
            const float v = cb[i * 64 + c];
            s += v * v;
        }
        g_cnorm[i] = s;
    }
}

// ---------------------------------------------------------------------------
// VQ argmin + one-hot scatter, FFMA2 inner product, LDS.128 codebook reads.
// z3 layout [64][21632]; score = ||c||^2 - 2 z.c  (||z||^2 row-constant).
// Strict < keeps first minimum (jnp.argmin tie-break).
// ---------------------------------------------------------------------------
__global__ __launch_bounds__(128) void argmin_onehot_kernel(
    const float* __restrict__ cb, float* __restrict__ out)
{
    __shared__ __align__(16) float cbs[128 * 64];
    __shared__ float cns[128];

    const int tid = threadIdx.x;
    const int n   = blockIdx.x * 128 + tid;

    ull zr2[32];
#pragma unroll
    for (int c = 0; c < 32; c++)
        zr2[c] = pack2(g_z3[(2 * c) * 21632 + n], g_z3[(2 * c + 1) * 21632 + n]);

    float best = 3.4e38f;
    int   bidx = 0;

    for (int t = 0; t < 4; t++) {
        __syncthreads();
        const float4* src = reinterpret_cast<const float4*>(cb + t * 128 * 64);
        float4* dst = reinterpret_cast<float4*>(cbs);
#pragma unroll
        for (int i = 0; i < 16; i++)
            dst[tid + i * 128] = src[tid + i * 128];
        cns[tid] = g_cnorm[t * 128 + tid];
        __syncthreads();

#pragma unroll 4
        for (int j = 0; j < 128; j++) {
            const ull* cr = reinterpret_cast<const ull*>(cbs + j * 64);
            ull d0 = 0, d1 = 0, d2 = 0, d3 = 0;
#pragma unroll
            for (int c = 0; c < 32; c += 4) {
                ulonglong2 c01 = *reinterpret_cast<const ulonglong2*>(cr + c);
                ulonglong2 c23 = *reinterpret_cast<const ulonglong2*>(cr + c + 2);
                ffma2(d0, zr2[c + 0], c01.x);
                ffma2(d1, zr2[c + 1], c01.y);
                ffma2(d2, zr2[c + 2], c23.x);
                ffma2(d3, zr2[c + 3], c23.y);
            }
            float2 p0 = unpack2(d0), p1 = unpack2(d1);
            float2 p2 = unpack2(d2), p3 = unpack2(d3);
            const float s = ((p0.x + p0.y) + (p1.x + p1.y))
                          + ((p2.x + p2.y) + (p3.x + p3.y));
            const float score = cns[j] - 2.f * s;
            const int gidx = t * 128 + j;
            if (score < best) { best = score; bidx = gidx; }
        }
    }

    const int b = n / 169;
    const int p = n % 169;
    out[((size_t)b * 512 + bidx) * 169 + p] = 1.0f;
}

// ---------------------------------------------------------------------------
extern "C" void kernel_launch(void* const* d_in, const int* in_sizes, int n_in,
                              void* d_out, int out_size)
{
    const float* x  = (const float*)d_in[0];
    const float* w1 = (const float*)d_in[1];
    const float* b1 = (const float*)d_in[2];
    const float* w2 = (const float*)d_in[3];
    const float* b2 = (const float*)d_in[4];
    const float* w3 = (const float*)d_in[5];
    const float* b3 = (const float*)d_in[6];
    const float* cb = (const float*)d_in[7];
    float* out = (float*)d_out;

    float *z1, *z2, *z3;
    cudaGetSymbolAddress((void**)&z1, g_z1);
    cudaGetSymbolAddress((void**)&z2, g_z2);
    cudaGetSymbolAddress((void**)&z3, g_z3);

    // output is a one-hot: zero it, scatter the ones later
    cudaMemsetAsync(out, 0, (size_t)out_size * sizeof(float));

    // conv1: 3->64, 8x8 s4 p2, 192->48, ReLU, NCHW.  N = 128*2304 = 294912
    conv_gemm_kernel<3, 8, 8, 192, 192, 48, 48, 4, 2, 64, true, 0>
        <<<dim3(294912 / 64, 1), 256>>>(x, w1, b1, z1);

    // conv2: 64->128, 6x6 s3 p2, 48->16, ReLU, NCHW.  N = 128*256 = 32768
    conv_gemm_kernel<64, 6, 6, 48, 48, 16, 16, 3, 2, 128, true, 0>
        <<<dim3(32768 / 64, 2), 256>>>(z1, w2, b2, z2);

    // conv3: 128->64, 4x4 s1 p0, 16->13, no ReLU, [C][N].  N = 128*169 = 21632
    conv_gemm_kernel<128, 4, 4, 16, 16, 13, 13, 1, 0, 64, false, 1>
        <<<dim3(21632 / 64, 1), 256>>>(z2, w3, b3, z3);

    cnorm_kernel<<<2, 256>>>(cb);

    argmin_onehot_kernel<<<21632 / 128, 128>>>(cb, out);
}